// round 11
// baseline (speedup 1.0000x reference)
#include <cuda_runtime.h>
#include <cuda_fp16.h>
#include <cstdint>

#define N_NODES 100000
#define N_EDGES 1600000
#define D 128
#define SCAN_BLK 1024
#define N_SCAN_BLKS ((N_NODES + SCAN_BLK - 1) / SCAN_BLK)   // 98

// ---------------- device-global scratch ----------------
__device__ __half g_h[(size_t)N_NODES * D]; // fp16: dinv[n] * (x @ W)[n]
__device__ float g_dinv[N_NODES];
__device__ int   g_degs[N_NODES];
__device__ int   g_cntd[N_NODES];
__device__ int   g_cur[N_NODES];             // bucket cursors (absolute, set by k_scan)
__device__ int   g_offp[N_NODES + 1];        // ABSOLUTE exclusive offsets + sentinel
__device__ volatile int g_aggs[128];         // per-block scan aggregates
__device__ int   g_ready;                    // published-aggregate counter
__device__ int   g_esrc[N_EDGES];

__device__ __forceinline__ uint32_t smem_u32(const void* p) {
    uint32_t a;
    asm("{ .reg .u64 t; cvta.to.shared.u64 t, %1; cvt.u32.u64 %0, t; }" : "=r"(a) : "l"(p));
    return a;
}
__device__ __forceinline__ void ldm4(uint32_t* r, uint32_t addr) {
    asm volatile("ldmatrix.sync.aligned.m8n8.x4.shared.b16 {%0,%1,%2,%3}, [%4];"
                 : "=r"(r[0]), "=r"(r[1]), "=r"(r[2]), "=r"(r[3]) : "r"(addr));
}
__device__ __forceinline__ void mma_f16(float* c, const uint32_t* a, uint32_t b0, uint32_t b1) {
    asm volatile("mma.sync.aligned.m16n8k16.row.col.f32.f16.f16.f32 "
                 "{%0,%1,%2,%3}, {%4,%5,%6,%7}, {%8,%9}, {%0,%1,%2,%3};"
                 : "+f"(c[0]), "+f"(c[1]), "+f"(c[2]), "+f"(c[3])
                 : "r"(a[0]), "r"(a[1]), "r"(a[2]), "r"(a[3]), "r"(b0), "r"(b1));
}
__device__ __forceinline__ void acc_h4(float4& acc, uint2 v) {
    float2 f0 = __half22float2(*(__half2*)&v.x);
    float2 f1 = __half22float2(*(__half2*)&v.y);
    acc.x += f0.x; acc.y += f0.y; acc.z += f1.x; acc.w += f1.y;
}

// ---------- 1) zero histograms (+ scan ready flag) ----------
__global__ void k_zero() {
    int i = blockIdx.x * blockDim.x + threadIdx.x;
    if (i < N_NODES) { g_degs[i] = 0; g_cntd[i] = 0; }
    if (i == 0) g_ready = 0;
}

// ---------- 2) histograms (4 edges/thread via int4, 8 independent REDs) ----------
__global__ void k_count(const int* __restrict__ ei) {
    int t = blockIdx.x * blockDim.x + threadIdx.x;
    if (t < N_EDGES / 4) {
        int4 s = ((const int4*)ei)[t];
        int4 d = ((const int4*)(ei + N_EDGES))[t];
        atomicAdd(&g_degs[s.x], 1); atomicAdd(&g_degs[s.y], 1);
        atomicAdd(&g_degs[s.z], 1); atomicAdd(&g_degs[s.w], 1);
        atomicAdd(&g_cntd[d.x], 1); atomicAdd(&g_cntd[d.y], 1);
        atomicAdd(&g_cntd[d.z], 1); atomicAdd(&g_cntd[d.w], 1);
    }
}

// ---------- 3) single-pass scan (+ dinv fold, + cursor init, + sentinel) ----------
// 98 blocks, all co-resident (98 < 148 SMs) -> global-flag sync is safe.
__global__ void __launch_bounds__(SCAN_BLK, 1)
k_scan() {
    __shared__ int warp_sums[32];
    __shared__ int s_prefix;
    const int tid = threadIdx.x;
    const int b = blockIdx.x;
    const int i = b * SCAN_BLK + tid;
    const int lane = tid & 31;
    const int wrp = tid >> 5;

    if (i < N_NODES) {
        int d = g_degs[i];
        g_dinv[i] = (d > 0) ? rsqrtf((float)d) : 0.0f;
    }

    int v = (i < N_NODES) ? g_cntd[i] : 0;

    // warp inclusive scan
    int x = v;
    #pragma unroll
    for (int o = 1; o < 32; o <<= 1) {
        int t = __shfl_up_sync(0xFFFFFFFFu, x, o);
        if (lane >= o) x += t;
    }
    if (lane == 31) warp_sums[wrp] = x;
    __syncthreads();
    if (tid < 32) {
        int y = warp_sums[tid];
        #pragma unroll
        for (int o = 1; o < 32; o <<= 1) {
            int t = __shfl_up_sync(0xFFFFFFFFu, y, o);
            if (tid >= o) y += t;
        }
        warp_sums[tid] = y;
    }
    __syncthreads();

    int incl = x + (wrp > 0 ? warp_sums[wrp - 1] : 0);
    int excl = incl - v;
    int block_total = warp_sums[31];

    // publish aggregate, then cross-block prefix via warp 0
    if (tid == 0) {
        g_aggs[b] = block_total;
        __threadfence();
        atomicAdd(&g_ready, 1);
    }
    if (tid < 32) {
        if (lane == 0) {
            while (atomicAdd(&g_ready, 0) < (int)gridDim.x) {}
        }
        __syncwarp();
        __threadfence();
        int p = 0;
        for (int j = lane; j < b; j += 32) p += g_aggs[j];
        #pragma unroll
        for (int o = 16; o; o >>= 1) p += __shfl_down_sync(0xFFFFFFFFu, p, o);
        if (lane == 0) s_prefix = p;
    }
    __syncthreads();

    if (i < N_NODES) {
        int off = excl + s_prefix;
        g_offp[i] = off;          // absolute exclusive offset
        g_cur[i]  = off;          // bucket cursor starts at the offset
    }
    if (i == N_NODES - 1) g_offp[N_NODES] = N_EDGES;   // CSR sentinel
}

// ---------- 4) bucket edges by dst (absolute cursors, 4 edges/thread) ----------
__global__ void k_bucket(const int* __restrict__ ei) {
    int t = blockIdx.x * blockDim.x + threadIdx.x;
    if (t < N_EDGES / 4) {
        int4 s = ((const int4*)ei)[t];
        int4 d = ((const int4*)(ei + N_EDGES))[t];
        // 4 independent returning atomics issued back-to-back (MLP=4)
        int p0 = atomicAdd(&g_cur[d.x], 1);
        int p1 = atomicAdd(&g_cur[d.y], 1);
        int p2 = atomicAdd(&g_cur[d.z], 1);
        int p3 = atomicAdd(&g_cur[d.w], 1);
        g_esrc[p0] = s.x;
        g_esrc[p1] = s.y;
        g_esrc[p2] = s.z;
        g_esrc[p3] = s.w;
    }
}

// ---------- 5) HMMA fp16 GEMM: g_h = half(dinv .* (x @ W)) ----------
#define KS 136                       // smem row stride in halves
#define ROWB (KS * 2)                // 272 bytes
#define OFF_A 0
#define OFF_B (128 * ROWB)           // 34816
#define SM_TOTAL (OFF_B + 128 * ROWB)  // 69632 B -> 2 CTAs/SM

__global__ void __launch_bounds__(256, 2)
k_gemm(const float* __restrict__ x, const float* __restrict__ w) {
    extern __shared__ __align__(16) char smem[];
    const int tid = threadIdx.x;
    const int lane = tid & 31;
    const int wid = tid >> 5;
    const int row0 = blockIdx.x * 128;

    // ---- stage A: 128 rows x 128 cols fp16 ----
    #pragma unroll
    for (int i = tid; i < 2048; i += 256) {
        int r = i >> 4, c8 = i & 15;
        int gr = row0 + r;
        float4 v0 = make_float4(0.f, 0.f, 0.f, 0.f), v1 = v0;
        if (gr < N_NODES) {
            const float4* xp = (const float4*)(x + (size_t)gr * D + c8 * 8);
            v0 = xp[0]; v1 = xp[1];
        }
        __half2 h0 = __floats2half2_rn(v0.x, v0.y);
        __half2 h1 = __floats2half2_rn(v0.z, v0.w);
        __half2 h2 = __floats2half2_rn(v1.x, v1.y);
        __half2 h3 = __floats2half2_rn(v1.z, v1.w);
        *(uint4*)(smem + OFF_A + r * ROWB + c8 * 16) =
            make_uint4(*(uint32_t*)&h0, *(uint32_t*)&h1, *(uint32_t*)&h2, *(uint32_t*)&h3);
    }

    // ---- stage B = W^T: [n][k] fp16 ----
    #pragma unroll
    for (int i = tid; i < 16384; i += 256) {
        int k = i >> 7, n = i & 127;
        float wv = w[i];                      // w[k*128 + n], coalesced
        *(__half*)(smem + OFF_B + n * ROWB + k * 2) = __float2half_rn(wv);
    }
    __syncthreads();

    const uint32_t sbase = smem_u32(smem);
    const int wm = (wid >> 1) * 32;
    const int wn = (wid & 1) * 64;

    const uint32_t aoff = sbase + OFF_A + (uint32_t)((wm + (lane & 15)) * ROWB + (lane >> 4) * 16);
    const uint32_t boff = sbase + OFF_B + (uint32_t)((wn + (lane & 15)) * ROWB + (lane >> 4) * 16);

    float acc[2][8][4];
    #pragma unroll
    for (int a = 0; a < 2; a++)
        #pragma unroll
        for (int b = 0; b < 8; b++)
            #pragma unroll
            for (int c = 0; c < 4; c++) acc[a][b][c] = 0.0f;

    #pragma unroll
    for (int ks = 0; ks < 8; ks++) {
        const uint32_t kb = ks * 32;
        uint32_t am[2][4];
        ldm4(am[0], aoff + kb);
        ldm4(am[1], aoff + 16 * ROWB + kb);
        #pragma unroll
        for (int pj = 0; pj < 4; pj++) {
            uint32_t bm[4];
            ldm4(bm, boff + pj * 16 * ROWB + kb);
            #pragma unroll
            for (int mi = 0; mi < 2; mi++) {
                mma_f16(acc[mi][pj * 2],     am[mi], bm[0], bm[2]);
                mma_f16(acc[mi][pj * 2 + 1], am[mi], bm[1], bm[3]);
            }
        }
    }

    // ---- epilogue: scale by dinv, convert to fp16, store half2 ----
    #pragma unroll
    for (int mi = 0; mi < 2; mi++) {
        int rl = row0 + wm + mi * 16 + (lane >> 2);
        int rh = rl + 8;
        float dvl = (rl < N_NODES) ? g_dinv[rl] : 0.0f;
        float dvh = (rh < N_NODES) ? g_dinv[rh] : 0.0f;
        #pragma unroll
        for (int nj = 0; nj < 8; nj++) {
            int col = wn + nj * 8 + (lane & 3) * 2;
            if (rl < N_NODES)
                *(__half2*)(g_h + (size_t)rl * D + col) =
                    __floats2half2_rn(dvl * acc[mi][nj][0], dvl * acc[mi][nj][1]);
            if (rh < N_NODES)
                *(__half2*)(g_h + (size_t)rh * D + col) =
                    __floats2half2_rn(dvh * acc[mi][nj][2], dvh * acc[mi][nj][3]);
        }
    }
}

// ---------- 6) gather: out[n] = bias + dinv[n] * sum_{s in bucket(n)} g_h[s] ----------
__global__ void k_gather(const float* __restrict__ bias, float* __restrict__ out) {
    int n = (blockIdx.x * blockDim.x + threadIdx.x) >> 5;
    int lane = threadIdx.x & 31;
    if (n >= N_NODES) return;

    int off = g_offp[n];
    int cnt = g_offp[n + 1] - off;   // CSR count from offsets
    float dn = g_dinv[n];

    float4 acc = make_float4(0.f, 0.f, 0.f, 0.f);
    int i = 0;
    for (; i + 4 <= cnt; i += 4) {
        int s0 = g_esrc[off + i], s1 = g_esrc[off + i + 1];
        int s2 = g_esrc[off + i + 2], s3 = g_esrc[off + i + 3];
        uint2 v0 = *((const uint2*)(g_h + (size_t)s0 * D) + lane);
        uint2 v1 = *((const uint2*)(g_h + (size_t)s1 * D) + lane);
        uint2 v2 = *((const uint2*)(g_h + (size_t)s2 * D) + lane);
        uint2 v3 = *((const uint2*)(g_h + (size_t)s3 * D) + lane);
        acc_h4(acc, v0); acc_h4(acc, v1); acc_h4(acc, v2); acc_h4(acc, v3);
    }
    for (; i < cnt; i++) {
        int s0 = g_esrc[off + i];
        uint2 v0 = *((const uint2*)(g_h + (size_t)s0 * D) + lane);
        acc_h4(acc, v0);
    }

    float4 b = ((const float4*)bias)[lane];
    *(float4*)(out + (size_t)n * D + lane * 4) =
        make_float4(b.x + dn * acc.x, b.y + dn * acc.y, b.z + dn * acc.z, b.w + dn * acc.w);
}

extern "C" void kernel_launch(void* const* d_in, const int* in_sizes, int n_in,
                              void* d_out, int out_size) {
    const float* x    = (const float*)d_in[0];
    const int*   ei   = (const int*)d_in[1];
    const float* w    = (const float*)d_in[2];
    const float* bias = (const float*)d_in[3];
    float*       out  = (float*)d_out;

    static bool init = false;
    if (!init) {
        cudaFuncSetAttribute(k_gemm, cudaFuncAttributeMaxDynamicSharedMemorySize, SM_TOTAL);
        init = true;
    }

    k_zero  <<<(N_NODES + 255) / 256, 256>>>();
    k_count <<<(N_EDGES / 4 + 255) / 256, 256>>>(ei);
    k_scan  <<<N_SCAN_BLKS, SCAN_BLK>>>();
    k_bucket<<<(N_EDGES / 4 + 255) / 256, 256>>>(ei);
    k_gemm  <<<(N_NODES + 127) / 128, 256, SM_TOTAL>>>(x, w);
    k_gather<<<(N_NODES * 32 + 255) / 256, 256>>>(bias, out);
}

// round 12
// speedup vs baseline: 1.0789x; 1.0789x over previous
#include <cuda_runtime.h>
#include <cuda_fp16.h>
#include <cstdint>

#define N_NODES 100000
#define N_EDGES 1600000
#define D 128
#define SCAN_BLK 1024
#define N_SCAN_BLKS ((N_NODES + SCAN_BLK - 1) / SCAN_BLK)   // 98
#define GEMM_BLKS ((N_NODES + 127) / 128)                    // 782
#define FUSED_BLKS (GEMM_BLKS * 3)                           // 2346: 1 gemm : 2 bucket

// ---------------- device-global scratch ----------------
__device__ __half g_h[(size_t)N_NODES * D]; // fp16: dinv[n] * (x @ W)[n]
__device__ float g_dinv[N_NODES];
__device__ int   g_degs[N_NODES];
__device__ int   g_cntd[N_NODES];
__device__ int   g_cur[N_NODES];             // bucket cursors (absolute, set by k_scan)
__device__ int   g_offp[N_NODES + 1];        // ABSOLUTE exclusive offsets + sentinel
__device__ volatile int g_aggs[128];         // per-block scan aggregates
__device__ int   g_ready;                    // published-aggregate counter
__device__ int   g_esrc[N_EDGES];

__device__ __forceinline__ uint32_t smem_u32(const void* p) {
    uint32_t a;
    asm("{ .reg .u64 t; cvta.to.shared.u64 t, %1; cvt.u32.u64 %0, t; }" : "=r"(a) : "l"(p));
    return a;
}
__device__ __forceinline__ void ldm4(uint32_t* r, uint32_t addr) {
    asm volatile("ldmatrix.sync.aligned.m8n8.x4.shared.b16 {%0,%1,%2,%3}, [%4];"
                 : "=r"(r[0]), "=r"(r[1]), "=r"(r[2]), "=r"(r[3]) : "r"(addr));
}
__device__ __forceinline__ void mma_f16(float* c, const uint32_t* a, uint32_t b0, uint32_t b1) {
    asm volatile("mma.sync.aligned.m16n8k16.row.col.f32.f16.f16.f32 "
                 "{%0,%1,%2,%3}, {%4,%5,%6,%7}, {%8,%9}, {%0,%1,%2,%3};"
                 : "+f"(c[0]), "+f"(c[1]), "+f"(c[2]), "+f"(c[3])
                 : "r"(a[0]), "r"(a[1]), "r"(a[2]), "r"(a[3]), "r"(b0), "r"(b1));
}
__device__ __forceinline__ void acc_h4(float4& acc, uint2 v) {
    float2 f0 = __half22float2(*(__half2*)&v.x);
    float2 f1 = __half22float2(*(__half2*)&v.y);
    acc.x += f0.x; acc.y += f0.y; acc.z += f1.x; acc.w += f1.y;
}

// ---------- 1) zero histograms (+ scan ready flag) ----------
__global__ void k_zero() {
    int i = blockIdx.x * blockDim.x + threadIdx.x;
    if (i < N_NODES) { g_degs[i] = 0; g_cntd[i] = 0; }
    if (i == 0) g_ready = 0;
}

// ---------- 2) histograms (4 edges/thread via int4, 8 independent REDs) ----------
__global__ void k_count(const int* __restrict__ ei) {
    int t = blockIdx.x * blockDim.x + threadIdx.x;
    if (t < N_EDGES / 4) {
        int4 s = ((const int4*)ei)[t];
        int4 d = ((const int4*)(ei + N_EDGES))[t];
        atomicAdd(&g_degs[s.x], 1); atomicAdd(&g_degs[s.y], 1);
        atomicAdd(&g_degs[s.z], 1); atomicAdd(&g_degs[s.w], 1);
        atomicAdd(&g_cntd[d.x], 1); atomicAdd(&g_cntd[d.y], 1);
        atomicAdd(&g_cntd[d.z], 1); atomicAdd(&g_cntd[d.w], 1);
    }
}

// ---------- 3) single-pass scan (+ dinv fold, + cursor init, + sentinel) ----------
// 98 blocks, all co-resident (98 < 148 SMs) -> global-flag sync is safe.
__global__ void __launch_bounds__(SCAN_BLK, 1)
k_scan() {
    __shared__ int warp_sums[32];
    __shared__ int s_prefix;
    const int tid = threadIdx.x;
    const int b = blockIdx.x;
    const int i = b * SCAN_BLK + tid;
    const int lane = tid & 31;
    const int wrp = tid >> 5;

    if (i < N_NODES) {
        int d = g_degs[i];
        g_dinv[i] = (d > 0) ? rsqrtf((float)d) : 0.0f;
    }

    int v = (i < N_NODES) ? g_cntd[i] : 0;

    int x = v;
    #pragma unroll
    for (int o = 1; o < 32; o <<= 1) {
        int t = __shfl_up_sync(0xFFFFFFFFu, x, o);
        if (lane >= o) x += t;
    }
    if (lane == 31) warp_sums[wrp] = x;
    __syncthreads();
    if (tid < 32) {
        int y = warp_sums[tid];
        #pragma unroll
        for (int o = 1; o < 32; o <<= 1) {
            int t = __shfl_up_sync(0xFFFFFFFFu, y, o);
            if (tid >= o) y += t;
        }
        warp_sums[tid] = y;
    }
    __syncthreads();

    int incl = x + (wrp > 0 ? warp_sums[wrp - 1] : 0);
    int excl = incl - v;
    int block_total = warp_sums[31];

    if (tid == 0) {
        g_aggs[b] = block_total;
        __threadfence();
        atomicAdd(&g_ready, 1);
    }
    if (tid < 32) {
        if (lane == 0) {
            while (atomicAdd(&g_ready, 0) < (int)gridDim.x) {}
        }
        __syncwarp();
        __threadfence();
        int p = 0;
        for (int j = lane; j < b; j += 32) p += g_aggs[j];
        #pragma unroll
        for (int o = 16; o; o >>= 1) p += __shfl_down_sync(0xFFFFFFFFu, p, o);
        if (lane == 0) s_prefix = p;
    }
    __syncthreads();

    if (i < N_NODES) {
        int off = excl + s_prefix;
        g_offp[i] = off;
        g_cur[i]  = off;
    }
    if (i == N_NODES - 1) g_offp[N_NODES] = N_EDGES;
}

// ---------- 4) FUSED gemm + bucket: per-block role, interleaved mod 3 ----------
// role 0 (782 blocks): HMMA fp16 GEMM tile  (tensor + smem pipes)
// role 1,2 (1564 blocks): bucket 1024 edges (LTS atomic pipe)
// Disjoint pipes -> concurrent execution hides bucket behind gemm.
#define KS 136                       // smem row stride in halves
#define ROWB (KS * 2)                // 272 bytes
#define OFF_A 0
#define OFF_B (128 * ROWB)           // 34816
#define SM_TOTAL (OFF_B + 128 * ROWB)  // 69632 B -> 2 CTAs/SM

__global__ void __launch_bounds__(256, 2)
k_gemm_bucket(const float* __restrict__ x, const float* __restrict__ w,
              const int* __restrict__ ei) {
    const int role = blockIdx.x % 3;
    const int g = blockIdx.x / 3;

    if (role != 0) {
        // ================= bucket path =================
        int t = (g * 2 + (role - 1)) * 256 + threadIdx.x;
        if (t < N_EDGES / 4) {
            int4 s = ((const int4*)ei)[t];
            int4 d = ((const int4*)(ei + N_EDGES))[t];
            int p0 = atomicAdd(&g_cur[d.x], 1);
            int p1 = atomicAdd(&g_cur[d.y], 1);
            int p2 = atomicAdd(&g_cur[d.z], 1);
            int p3 = atomicAdd(&g_cur[d.w], 1);
            g_esrc[p0] = s.x;
            g_esrc[p1] = s.y;
            g_esrc[p2] = s.z;
            g_esrc[p3] = s.w;
        }
        return;
    }

    // ================= gemm path =================
    extern __shared__ __align__(16) char smem[];
    const int tid = threadIdx.x;
    const int lane = tid & 31;
    const int wid = tid >> 5;
    const int row0 = g * 128;

    // ---- stage A: 128 rows x 128 cols fp16 ----
    #pragma unroll
    for (int i = tid; i < 2048; i += 256) {
        int r = i >> 4, c8 = i & 15;
        int gr = row0 + r;
        float4 v0 = make_float4(0.f, 0.f, 0.f, 0.f), v1 = v0;
        if (gr < N_NODES) {
            const float4* xp = (const float4*)(x + (size_t)gr * D + c8 * 8);
            v0 = xp[0]; v1 = xp[1];
        }
        __half2 h0 = __floats2half2_rn(v0.x, v0.y);
        __half2 h1 = __floats2half2_rn(v0.z, v0.w);
        __half2 h2 = __floats2half2_rn(v1.x, v1.y);
        __half2 h3 = __floats2half2_rn(v1.z, v1.w);
        *(uint4*)(smem + OFF_A + r * ROWB + c8 * 16) =
            make_uint4(*(uint32_t*)&h0, *(uint32_t*)&h1, *(uint32_t*)&h2, *(uint32_t*)&h3);
    }

    // ---- stage B = W^T: [n][k] fp16 ----
    #pragma unroll
    for (int i = tid; i < 16384; i += 256) {
        int k = i >> 7, n = i & 127;
        float wv = w[i];                      // w[k*128 + n], coalesced
        *(__half*)(smem + OFF_B + n * ROWB + k * 2) = __float2half_rn(wv);
    }
    __syncthreads();

    const uint32_t sbase = smem_u32(smem);
    const int wm = (wid >> 1) * 32;
    const int wn = (wid & 1) * 64;

    const uint32_t aoff = sbase + OFF_A + (uint32_t)((wm + (lane & 15)) * ROWB + (lane >> 4) * 16);
    const uint32_t boff = sbase + OFF_B + (uint32_t)((wn + (lane & 15)) * ROWB + (lane >> 4) * 16);

    float acc[2][8][4];
    #pragma unroll
    for (int a = 0; a < 2; a++)
        #pragma unroll
        for (int b = 0; b < 8; b++)
            #pragma unroll
            for (int c = 0; c < 4; c++) acc[a][b][c] = 0.0f;

    #pragma unroll
    for (int ks = 0; ks < 8; ks++) {
        const uint32_t kb = ks * 32;
        uint32_t am[2][4];
        ldm4(am[0], aoff + kb);
        ldm4(am[1], aoff + 16 * ROWB + kb);
        #pragma unroll
        for (int pj = 0; pj < 4; pj++) {
            uint32_t bm[4];
            ldm4(bm, boff + pj * 16 * ROWB + kb);
            #pragma unroll
            for (int mi = 0; mi < 2; mi++) {
                mma_f16(acc[mi][pj * 2],     am[mi], bm[0], bm[2]);
                mma_f16(acc[mi][pj * 2 + 1], am[mi], bm[1], bm[3]);
            }
        }
    }

    // ---- epilogue: scale by dinv, convert to fp16, store half2 ----
    #pragma unroll
    for (int mi = 0; mi < 2; mi++) {
        int rl = row0 + wm + mi * 16 + (lane >> 2);
        int rh = rl + 8;
        float dvl = (rl < N_NODES) ? g_dinv[rl] : 0.0f;
        float dvh = (rh < N_NODES) ? g_dinv[rh] : 0.0f;
        #pragma unroll
        for (int nj = 0; nj < 8; nj++) {
            int col = wn + nj * 8 + (lane & 3) * 2;
            if (rl < N_NODES)
                *(__half2*)(g_h + (size_t)rl * D + col) =
                    __floats2half2_rn(dvl * acc[mi][nj][0], dvl * acc[mi][nj][1]);
            if (rh < N_NODES)
                *(__half2*)(g_h + (size_t)rh * D + col) =
                    __floats2half2_rn(dvh * acc[mi][nj][2], dvh * acc[mi][nj][3]);
        }
    }
}

// ---------- 5) gather: out[n] = bias + dinv[n] * sum_{s in bucket(n)} g_h[s] ----------
__global__ void k_gather(const float* __restrict__ bias, float* __restrict__ out) {
    int n = (blockIdx.x * blockDim.x + threadIdx.x) >> 5;
    int lane = threadIdx.x & 31;
    if (n >= N_NODES) return;

    int off = g_offp[n];
    int cnt = g_offp[n + 1] - off;   // CSR count from offsets
    float dn = g_dinv[n];

    float4 acc = make_float4(0.f, 0.f, 0.f, 0.f);
    int i = 0;
    for (; i + 4 <= cnt; i += 4) {
        int s0 = g_esrc[off + i], s1 = g_esrc[off + i + 1];
        int s2 = g_esrc[off + i + 2], s3 = g_esrc[off + i + 3];
        uint2 v0 = *((const uint2*)(g_h + (size_t)s0 * D) + lane);
        uint2 v1 = *((const uint2*)(g_h + (size_t)s1 * D) + lane);
        uint2 v2 = *((const uint2*)(g_h + (size_t)s2 * D) + lane);
        uint2 v3 = *((const uint2*)(g_h + (size_t)s3 * D) + lane);
        acc_h4(acc, v0); acc_h4(acc, v1); acc_h4(acc, v2); acc_h4(acc, v3);
    }
    for (; i < cnt; i++) {
        int s0 = g_esrc[off + i];
        uint2 v0 = *((const uint2*)(g_h + (size_t)s0 * D) + lane);
        acc_h4(acc, v0);
    }

    float4 b = ((const float4*)bias)[lane];
    *(float4*)(out + (size_t)n * D + lane * 4) =
        make_float4(b.x + dn * acc.x, b.y + dn * acc.y, b.z + dn * acc.z, b.w + dn * acc.w);
}

extern "C" void kernel_launch(void* const* d_in, const int* in_sizes, int n_in,
                              void* d_out, int out_size) {
    const float* x    = (const float*)d_in[0];
    const int*   ei   = (const int*)d_in[1];
    const float* w    = (const float*)d_in[2];
    const float* bias = (const float*)d_in[3];
    float*       out  = (float*)d_out;

    static bool init = false;
    if (!init) {
        cudaFuncSetAttribute(k_gemm_bucket, cudaFuncAttributeMaxDynamicSharedMemorySize, SM_TOTAL);
        init = true;
    }

    k_zero       <<<(N_NODES + 255) / 256, 256>>>();
    k_count      <<<(N_EDGES / 4 + 255) / 256, 256>>>(ei);
    k_scan       <<<N_SCAN_BLKS, SCAN_BLK>>>();
    k_gemm_bucket<<<FUSED_BLKS, 256, SM_TOTAL>>>(x, w, ei);
    k_gather     <<<(N_NODES * 32 + 255) / 256, 256>>>(bias, out);
}

// round 13
// speedup vs baseline: 1.1154x; 1.0338x over previous
#include <cuda_runtime.h>
#include <cuda_fp16.h>
#include <cstdint>

#define N_NODES 100000
#define N_EDGES 1600000
#define D 128
#define SCAN_BLK 1024
#define N_SCAN_BLKS ((N_NODES + SCAN_BLK - 1) / SCAN_BLK)   // 98
#define GEMM_BLKS ((N_NODES + 63) / 64)                      // 1563
#define BUCKET_BLKS ((N_EDGES / 4 + 255) / 256)              // 1563
#define FUSED_BLKS (GEMM_BLKS + BUCKET_BLKS)                 // 3126, parity roles

// ---------------- device-global scratch ----------------
__device__ __half g_h[(size_t)N_NODES * D]; // fp16: dinv[n] * (x @ W)[n]
__device__ __align__(16) __half g_wT[128 * 136];  // W^T fp16, 272B-stride layout
__device__ float g_dinv[N_NODES];
__device__ int   g_degs[N_NODES];
__device__ int   g_cntd[N_NODES];
__device__ int   g_cur[N_NODES];             // bucket cursors (absolute, set by k_scan)
__device__ int   g_offp[N_NODES + 1];        // ABSOLUTE exclusive offsets + sentinel
__device__ volatile int g_aggs[128];         // per-block scan aggregates
__device__ int   g_ready;                    // published-aggregate counter
__device__ int   g_esrc[N_EDGES];

__device__ __forceinline__ uint32_t smem_u32(const void* p) {
    uint32_t a;
    asm("{ .reg .u64 t; cvta.to.shared.u64 t, %1; cvt.u32.u64 %0, t; }" : "=r"(a) : "l"(p));
    return a;
}
__device__ __forceinline__ void ldm4(uint32_t* r, uint32_t addr) {
    asm volatile("ldmatrix.sync.aligned.m8n8.x4.shared.b16 {%0,%1,%2,%3}, [%4];"
                 : "=r"(r[0]), "=r"(r[1]), "=r"(r[2]), "=r"(r[3]) : "r"(addr));
}
__device__ __forceinline__ void mma_f16(float* c, const uint32_t* a, uint32_t b0, uint32_t b1) {
    asm volatile("mma.sync.aligned.m16n8k16.row.col.f32.f16.f16.f32 "
                 "{%0,%1,%2,%3}, {%4,%5,%6,%7}, {%8,%9}, {%0,%1,%2,%3};"
                 : "+f"(c[0]), "+f"(c[1]), "+f"(c[2]), "+f"(c[3])
                 : "r"(a[0]), "r"(a[1]), "r"(a[2]), "r"(a[3]), "r"(b0), "r"(b1));
}
__device__ __forceinline__ void acc_h4(float4& acc, uint2 v) {
    float2 f0 = __half22float2(*(__half2*)&v.x);
    float2 f1 = __half22float2(*(__half2*)&v.y);
    acc.x += f0.x; acc.y += f0.y; acc.z += f1.x; acc.w += f1.y;
}

// ---------- 1) zero histograms (+ scan ready flag) ----------
__global__ void k_zero() {
    int i = blockIdx.x * blockDim.x + threadIdx.x;
    if (i < N_NODES) { g_degs[i] = 0; g_cntd[i] = 0; }
    if (i == 0) g_ready = 0;
}

// ---------- 2) histograms (+ one-time W^T fp16 conversion) ----------
__global__ void k_count(const int* __restrict__ ei, const float* __restrict__ w) {
    int t = blockIdx.x * blockDim.x + threadIdx.x;
    if (t < N_EDGES / 4) {
        int4 s = ((const int4*)ei)[t];
        int4 d = ((const int4*)(ei + N_EDGES))[t];
        atomicAdd(&g_degs[s.x], 1); atomicAdd(&g_degs[s.y], 1);
        atomicAdd(&g_degs[s.z], 1); atomicAdd(&g_degs[s.w], 1);
        atomicAdd(&g_cntd[d.x], 1); atomicAdd(&g_cntd[d.y], 1);
        atomicAdd(&g_cntd[d.z], 1); atomicAdd(&g_cntd[d.w], 1);
    }
    if (t < 16384) {
        int k = t >> 7, n = t & 127;
        g_wT[n * 136 + k] = __float2half_rn(w[t]);   // w[k*128+n]
    }
}

// ---------- 3) single-pass scan (+ dinv fold, + cursor init, + sentinel) ----------
__global__ void __launch_bounds__(SCAN_BLK, 1)
k_scan() {
    __shared__ int warp_sums[32];
    __shared__ int s_prefix;
    const int tid = threadIdx.x;
    const int b = blockIdx.x;
    const int i = b * SCAN_BLK + tid;
    const int lane = tid & 31;
    const int wrp = tid >> 5;

    if (i < N_NODES) {
        int d = g_degs[i];
        g_dinv[i] = (d > 0) ? rsqrtf((float)d) : 0.0f;
    }

    int v = (i < N_NODES) ? g_cntd[i] : 0;

    int x = v;
    #pragma unroll
    for (int o = 1; o < 32; o <<= 1) {
        int t = __shfl_up_sync(0xFFFFFFFFu, x, o);
        if (lane >= o) x += t;
    }
    if (lane == 31) warp_sums[wrp] = x;
    __syncthreads();
    if (tid < 32) {
        int y = warp_sums[tid];
        #pragma unroll
        for (int o = 1; o < 32; o <<= 1) {
            int t = __shfl_up_sync(0xFFFFFFFFu, y, o);
            if (tid >= o) y += t;
        }
        warp_sums[tid] = y;
    }
    __syncthreads();

    int incl = x + (wrp > 0 ? warp_sums[wrp - 1] : 0);
    int excl = incl - v;
    int block_total = warp_sums[31];

    if (tid == 0) {
        g_aggs[b] = block_total;
        __threadfence();
        atomicAdd(&g_ready, 1);
    }
    if (tid < 32) {
        if (lane == 0) {
            while (atomicAdd(&g_ready, 0) < (int)gridDim.x) {}
        }
        __syncwarp();
        __threadfence();
        int p = 0;
        for (int j = lane; j < b; j += 32) p += g_aggs[j];
        #pragma unroll
        for (int o = 16; o; o >>= 1) p += __shfl_down_sync(0xFFFFFFFFu, p, o);
        if (lane == 0) s_prefix = p;
    }
    __syncthreads();

    if (i < N_NODES) {
        int off = excl + s_prefix;
        g_offp[i] = off;
        g_cur[i]  = off;
    }
    if (i == N_NODES - 1) g_offp[N_NODES] = N_EDGES;
}

// ---------- 4) FUSED gemm + bucket (parity roles, 3 CTAs/SM) ----------
// even blocks: 64-row HMMA gemm tile; odd blocks: bucket 1024 edges.
#define KS 136                       // smem row stride in halves
#define ROWB (KS * 2)                // 272 bytes
#define OFF_A 0
#define OFF_B (64 * ROWB)            // 17408
#define SM_TOTAL (OFF_B + 128 * ROWB)  // 52224 B -> 3 CTAs/SM

__global__ void __launch_bounds__(256, 3)
k_gemm_bucket(const float* __restrict__ x, const int* __restrict__ ei) {
    const int role = blockIdx.x & 1;
    const int g = blockIdx.x >> 1;

    if (role) {
        // ================= bucket path =================
        int t = g * 256 + threadIdx.x;
        if (t < N_EDGES / 4) {
            int4 s = ((const int4*)ei)[t];
            int4 d = ((const int4*)(ei + N_EDGES))[t];
            int p0 = atomicAdd(&g_cur[d.x], 1);
            int p1 = atomicAdd(&g_cur[d.y], 1);
            int p2 = atomicAdd(&g_cur[d.z], 1);
            int p3 = atomicAdd(&g_cur[d.w], 1);
            g_esrc[p0] = s.x;
            g_esrc[p1] = s.y;
            g_esrc[p2] = s.z;
            g_esrc[p3] = s.w;
        }
        return;
    }

    // ================= gemm path: 64 rows x 128 cols =================
    extern __shared__ __align__(16) char smem[];
    const int tid = threadIdx.x;
    const int lane = tid & 31;
    const int wid = tid >> 5;
    const int row0 = g * 64;
    if (row0 >= N_NODES) return;

    // ---- stage A: 64 rows x 128 cols fp16 ----
    #pragma unroll
    for (int i = tid; i < 1024; i += 256) {
        int r = i >> 4, c8 = i & 15;
        int gr = row0 + r;
        float4 v0 = make_float4(0.f, 0.f, 0.f, 0.f), v1 = v0;
        if (gr < N_NODES) {
            const float4* xp = (const float4*)(x + (size_t)gr * D + c8 * 8);
            v0 = xp[0]; v1 = xp[1];
        }
        __half2 h0 = __floats2half2_rn(v0.x, v0.y);
        __half2 h1 = __floats2half2_rn(v0.z, v0.w);
        __half2 h2 = __floats2half2_rn(v1.x, v1.y);
        __half2 h3 = __floats2half2_rn(v1.z, v1.w);
        *(uint4*)(smem + OFF_A + r * ROWB + c8 * 16) =
            make_uint4(*(uint32_t*)&h0, *(uint32_t*)&h1, *(uint32_t*)&h2, *(uint32_t*)&h3);
    }

    // ---- stage B: straight copy of pre-converted W^T (34816 B = 2176 uint4) ----
    {
        const uint4* src = (const uint4*)g_wT;
        uint4* dst = (uint4*)(smem + OFF_B);
        #pragma unroll
        for (int i = tid; i < 2176; i += 256) dst[i] = src[i];
    }
    __syncthreads();

    const uint32_t sbase = smem_u32(smem);
    const int wm = (wid >> 1) * 16;           // warp row base: 0,16,32,48
    const int wn = (wid & 1) * 64;            // warp col base: 0,64

    const uint32_t aoff = sbase + OFF_A + (uint32_t)((wm + (lane & 15)) * ROWB + (lane >> 4) * 16);
    const uint32_t boff = sbase + OFF_B + (uint32_t)((wn + (lane & 15)) * ROWB + (lane >> 4) * 16);

    float acc[8][4];
    #pragma unroll
    for (int b = 0; b < 8; b++)
        #pragma unroll
        for (int c = 0; c < 4; c++) acc[b][c] = 0.0f;

    #pragma unroll
    for (int ks = 0; ks < 8; ks++) {
        const uint32_t kb = ks * 32;
        uint32_t am[4];
        ldm4(am, aoff + kb);
        #pragma unroll
        for (int pj = 0; pj < 4; pj++) {
            uint32_t bm[4];
            ldm4(bm, boff + pj * 16 * ROWB + kb);
            mma_f16(acc[pj * 2],     am, bm[0], bm[2]);
            mma_f16(acc[pj * 2 + 1], am, bm[1], bm[3]);
        }
    }

    // ---- epilogue: scale by dinv, convert to fp16, store half2 ----
    {
        int rl = row0 + wm + (lane >> 2);
        int rh = rl + 8;
        float dvl = (rl < N_NODES) ? g_dinv[rl] : 0.0f;
        float dvh = (rh < N_NODES) ? g_dinv[rh] : 0.0f;
        #pragma unroll
        for (int nj = 0; nj < 8; nj++) {
            int col = wn + nj * 8 + (lane & 3) * 2;
            if (rl < N_NODES)
                *(__half2*)(g_h + (size_t)rl * D + col) =
                    __floats2half2_rn(dvl * acc[nj][0], dvl * acc[nj][1]);
            if (rh < N_NODES)
                *(__half2*)(g_h + (size_t)rh * D + col) =
                    __floats2half2_rn(dvh * acc[nj][2], dvh * acc[nj][3]);
        }
    }
}

// ---------- 5) gather: out[n] = bias + dinv[n] * sum_{s in bucket(n)} g_h[s] ----------
__global__ void k_gather(const float* __restrict__ bias, float* __restrict__ out) {
    int n = (blockIdx.x * blockDim.x + threadIdx.x) >> 5;
    int lane = threadIdx.x & 31;
    if (n >= N_NODES) return;

    int off = g_offp[n];
    int cnt = g_offp[n + 1] - off;   // CSR count from offsets
    float dn = g_dinv[n];

    float4 acc = make_float4(0.f, 0.f, 0.f, 0.f);
    int i = 0;
    for (; i + 4 <= cnt; i += 4) {
        int s0 = g_esrc[off + i], s1 = g_esrc[off + i + 1];
        int s2 = g_esrc[off + i + 2], s3 = g_esrc[off + i + 3];
        uint2 v0 = *((const uint2*)(g_h + (size_t)s0 * D) + lane);
        uint2 v1 = *((const uint2*)(g_h + (size_t)s1 * D) + lane);
        uint2 v2 = *((const uint2*)(g_h + (size_t)s2 * D) + lane);
        uint2 v3 = *((const uint2*)(g_h + (size_t)s3 * D) + lane);
        acc_h4(acc, v0); acc_h4(acc, v1); acc_h4(acc, v2); acc_h4(acc, v3);
    }
    for (; i < cnt; i++) {
        int s0 = g_esrc[off + i];
        uint2 v0 = *((const uint2*)(g_h + (size_t)s0 * D) + lane);
        acc_h4(acc, v0);
    }

    float4 b = ((const float4*)bias)[lane];
    *(float4*)(out + (size_t)n * D + lane * 4) =
        make_float4(b.x + dn * acc.x, b.y + dn * acc.y, b.z + dn * acc.z, b.w + dn * acc.w);
}

extern "C" void kernel_launch(void* const* d_in, const int* in_sizes, int n_in,
                              void* d_out, int out_size) {
    const float* x    = (const float*)d_in[0];
    const int*   ei   = (const int*)d_in[1];
    const float* w    = (const float*)d_in[2];
    const float* bias = (const float*)d_in[3];
    float*       out  = (float*)d_out;

    static bool init = false;
    if (!init) {
        cudaFuncSetAttribute(k_gemm_bucket, cudaFuncAttributeMaxDynamicSharedMemorySize, SM_TOTAL);
        init = true;
    }

    k_zero       <<<(N_NODES + 255) / 256, 256>>>();
    k_count      <<<(N_EDGES / 4 + 255) / 256, 256>>>(ei, w);
    k_scan       <<<N_SCAN_BLKS, SCAN_BLK>>>();
    k_gemm_bucket<<<FUSED_BLKS, 256, SM_TOTAL>>>(x, ei);
    k_gather     <<<(N_NODES * 32 + 255) / 256, 256>>>(bias, out);
}